// round 5
// baseline (speedup 1.0000x reference)
#include <cuda_runtime.h>

#define NB     8
#define NATOM  512
#define NFEAT  42
#define NNEIGH 100
#define NPT    256
#define NH1    64
#define NH2    32

// scratch for dE (input gradient), computed by ei_kernel, consumed by force_kernel
__device__ float g_dE[NB * NATOM * NFEAT];

// ---------------------------------------------------------------------------
// Kernel 1: per-atom MLP forward + backward, warp-per-atom.
// Grid: 512 blocks x 256 threads = 8 warps/block, 1 atom per warp.
// Weights cached in SMEM with padded strides (43 / 65) for conflict-free LDS.
// No block-wide syncs after weight staging; only __syncwarp in compute path.
// ---------------------------------------------------------------------------
__global__ __launch_bounds__(256) void ei_kernel(
    const float* __restrict__ image,
    const float* __restrict__ W0, const float* __restrict__ b0,
    const float* __restrict__ W1, const float* __restrict__ b1,
    const float* __restrict__ W2, const float* __restrict__ b2,
    float* __restrict__ out)
{
    __shared__ float sW0[NH1 * 43];   // 64 rows, stride 43 (pad: 11 mod 32 coprime)
    __shared__ float sW1[NH2 * 65];   // 32 rows, stride 65 (pad: 65 mod 32 = 1)
    __shared__ float sW2[NH2];
    __shared__ float sb0[NH1];
    __shared__ float sb1[NH2];
    __shared__ float sb2v;
    __shared__ float sx [8][NFEAT];
    __shared__ float sh1[8][NH1];
    __shared__ float sg2[8][NH2];
    __shared__ float sg1[8][NH1];

    const int tid = threadIdx.x;
    const int w   = tid >> 5;        // warp = atom within block
    const int l   = tid & 31;        // lane

    const int base = blockIdx.x * 8;         // global atom index b*NATOM + a
    const int b    = base / NATOM;
    const int a0   = base % NATOM;
    const int t    = a0 / NPT;               // atom type (8 | 256, never crosses)

    for (int i = tid; i < NH1 * NFEAT; i += 256) {
        int r = i / NFEAT, c = i - r * NFEAT;
        sW0[r * 43 + c] = W0[t * NH1 * NFEAT + i];
    }
    for (int i = tid; i < NH2 * NH1; i += 256) {
        int r = i >> 6, c = i & 63;
        sW1[r * 65 + c] = W1[t * NH2 * NH1 + i];
    }
    if (tid < NH2) sW2[tid] = W2[t * NH2 + tid];
    if (tid < NH1) sb0[tid] = b0[t * NH1 + tid];
    if (tid < NH2) sb1[tid] = b1[t * NH2 + tid];
    if (tid == 0)  sb2v = b2[t];
    __syncthreads();

    const int gidx = b * NATOM + (a0 + w);

    // load x (42 features)
    if (l < NFEAT)      sx[w][l]      = image[(long)gidx * NFEAT + l];
    if (l < NFEAT - 32) sx[w][32 + l] = image[(long)gidx * NFEAT + 32 + l];
    __syncwarp();

    // h1 = tanh(W0 x + b0): 2 neurons/lane
    float s1 = sb0[l], s2 = sb0[32 + l];
    #pragma unroll
    for (int f = 0; f < NFEAT; f++) {
        const float xv = sx[w][f];
        s1 += xv * sW0[l * 43 + f];
        s2 += xv * sW0[(32 + l) * 43 + f];
    }
    const float h1a = tanhf(s1), h1b = tanhf(s2);
    sh1[w][l] = h1a; sh1[w][32 + l] = h1b;
    __syncwarp();

    // h2 = tanh(W1 h1 + b1), g2 = W2 .* (1 - h2^2): 1 neuron/lane
    float s = sb1[l];
    #pragma unroll
    for (int i = 0; i < NH1; i++) s += sh1[w][i] * sW1[l * 65 + i];
    const float h2 = tanhf(s);
    const float w2v = sW2[l];
    sg2[w][l] = w2v * (1.0f - h2 * h2);

    // Ei = W2 . h2 + b2 (warp reduce)
    float v = h2 * w2v;
    #pragma unroll
    for (int o = 16; o > 0; o >>= 1) v += __shfl_down_sync(0xffffffffu, v, o);
    if (l == 0) out[8 + gidx] = v + sb2v;
    __syncwarp();

    // g1 = (W1^T g2) .* (1 - h1^2): 2 entries/lane
    float t1 = 0.0f, t2 = 0.0f;
    #pragma unroll
    for (int j = 0; j < NH2; j++) {
        const float gv = sg2[w][j];
        t1 += gv * sW1[j * 65 + l];
        t2 += gv * sW1[j * 65 + 32 + l];
    }
    sg1[w][l]      = t1 * (1.0f - h1a * h1a);
    sg1[w][32 + l] = t2 * (1.0f - h1b * h1b);
    __syncwarp();

    // dx = W0^T g1: feature f = l (all lanes) and f = 32+l (lanes < 10)
    const int c2 = (l < NFEAT - 32) ? (32 + l) : 0;   // guard smem OOB
    float d1 = 0.0f, d2 = 0.0f;
    #pragma unroll
    for (int i = 0; i < NH1; i++) {
        const float gv = sg1[w][i];
        d1 += gv * sW0[i * 43 + l];
        d2 += gv * sW0[i * 43 + c2];
    }
    if (l < NFEAT)      g_dE[(long)gidx * NFEAT + l]      = d1;
    if (l < NFEAT - 32) g_dE[(long)gidx * NFEAT + 32 + l] = d2;
}

// ---------------------------------------------------------------------------
// Kernel 2: Force[b,a,k] = sum_{n,f} dE_padded[b, neighbor[b,a,n], f]
//                                    * dfeat[b,a,n,f,k]
// One block per atom (4096 blocks, 256 threads). Gathered dE tile staged in
// SMEM, dfeat streamed with LDG.128. Blocks 0..7 additionally compute Etot
// (deterministic fixed-order reduction), replacing the separate etot kernel.
// ---------------------------------------------------------------------------
__global__ __launch_bounds__(256) void force_kernel(
    const float* __restrict__ dfeat,
    const int* __restrict__ neighbor,
    float* __restrict__ out)
{
    __shared__ __align__(16) float sg[NNEIGH * NFEAT];  // 4200 floats
    __shared__ int sn[NNEIGH];
    __shared__ float red[8][3];
    __shared__ float sred[8];

    const int tid  = threadIdx.x;
    const int gidx = blockIdx.x;             // b*NATOM + a
    const int b    = gidx / NATOM;

    if (tid < NNEIGH)
        sn[tid] = neighbor[(long)gidx * NNEIGH + tid];

    // fused Etot partial (blocks 0..7 only): fixed-order, deterministic
    if (gidx < NB) {
        const float* Ei = out + 8 + (long)gidx * NATOM;
        float v = Ei[tid] + Ei[tid + 256];
        #pragma unroll
        for (int o = 16; o > 0; o >>= 1) v += __shfl_down_sync(0xffffffffu, v, o);
        if ((tid & 31) == 0) sred[tid >> 5] = v;
    }
    __syncthreads();

    // Gather dE rows (index 0 -> zero pad row); L2-resident
    for (int i = tid; i < NNEIGH * NFEAT; i += 256) {
        const int n = i / NFEAT;
        const int f = i - n * NFEAT;
        const int j = sn[n];
        sg[i] = j ? g_dE[((long)b * NATOM + (j - 1)) * NFEAT + f] : 0.0f;
    }
    __syncthreads();

    if (gidx < NB && tid == 0) {
        float s = 0.0f;
        #pragma unroll
        for (int ww = 0; ww < 8; ww++) s += sred[ww];
        out[gidx] = s;
    }

    const float4* df = (const float4*)(dfeat + (long)gidx * (NNEIGH * NFEAT * 3));
    float ax = 0.0f, ay = 0.0f, az = 0.0f;

    // 1050 groups of 4 (n,f)-pairs; elements 12q..12q+11 decompose as:
    // v0 = {p0k0,p0k1,p0k2,p1k0}, v1 = {p1k1,p1k2,p2k0,p2k1}, v2 = {p2k2,p3k0,p3k1,p3k2}
    for (int q = tid; q < (NNEIGH * NFEAT) / 4; q += 256) {
        const float4 v0 = df[q * 3 + 0];
        const float4 v1 = df[q * 3 + 1];
        const float4 v2 = df[q * 3 + 2];
        const float4 g4 = *(const float4*)(&sg[4 * q]);
        ax += g4.x * v0.x + g4.y * v0.w + g4.z * v1.z + g4.w * v2.y;
        ay += g4.x * v0.y + g4.y * v1.x + g4.z * v1.w + g4.w * v2.z;
        az += g4.x * v0.z + g4.y * v1.y + g4.z * v2.x + g4.w * v2.w;
    }

    #pragma unroll
    for (int o = 16; o > 0; o >>= 1) {
        ax += __shfl_down_sync(0xffffffffu, ax, o);
        ay += __shfl_down_sync(0xffffffffu, ay, o);
        az += __shfl_down_sync(0xffffffffu, az, o);
    }
    const int w = tid >> 5, l = tid & 31;
    if (l == 0) { red[w][0] = ax; red[w][1] = ay; red[w][2] = az; }
    __syncthreads();
    if (tid < 3) {
        float s = 0.0f;
        #pragma unroll
        for (int ww = 0; ww < 8; ww++) s += red[ww][tid];
        out[8 + NB * NATOM + (long)gidx * 3 + tid] = s;
    }
}

// ---------------------------------------------------------------------------
// Launch: out layout = [Etot(8) | Ei(4096) | Force(12288)] = 16392 f32
// ---------------------------------------------------------------------------
extern "C" void kernel_launch(void* const* d_in, const int* in_sizes, int n_in,
                              void* d_out, int out_size)
{
    const float* image    = (const float*)d_in[0];
    const float* dfeat    = (const float*)d_in[1];
    const int*   neighbor = (const int*)d_in[2];
    // d_in[3] = natoms_img (unused)
    const float* W0 = (const float*)d_in[4];
    const float* b0 = (const float*)d_in[5];
    const float* W1 = (const float*)d_in[6];
    const float* b1 = (const float*)d_in[7];
    const float* W2 = (const float*)d_in[8];
    const float* b2 = (const float*)d_in[9];
    float* out = (float*)d_out;

    ei_kernel<<<(NB * NATOM) / 8, 256>>>(image, W0, b0, W1, b1, W2, b2, out);
    force_kernel<<<NB * NATOM, 256>>>(dfeat, neighbor, out);
}

// round 7
// speedup vs baseline: 1.3008x; 1.3008x over previous
#include <cuda_runtime.h>

#define NB     8
#define NATOM  512
#define NFEAT  42
#define NNEIGH 100
#define NPT    256
#define NH1    64
#define NH2    32

#define FT     384            // force kernel threads (divisible by 3!)
#define NPAIR  (NNEIGH*NFEAT) // 4200
#define NQ     (NPAIR*3/4)    // 3150 float4s per atom tile

// scratch for dE (input gradient), computed by ei_kernel, consumed by force_kernel
__device__ float g_dE[NB * NATOM * NFEAT];

// ---------------------------------------------------------------------------
// Kernel 1: per-atom MLP forward + backward, warp-per-atom.
// ---------------------------------------------------------------------------
__global__ __launch_bounds__(256) void ei_kernel(
    const float* __restrict__ image,
    const float* __restrict__ W0, const float* __restrict__ b0,
    const float* __restrict__ W1, const float* __restrict__ b1,
    const float* __restrict__ W2, const float* __restrict__ b2,
    float* __restrict__ out)
{
    __shared__ float sW0[NH1 * 43];
    __shared__ float sW1[NH2 * 65];
    __shared__ float sW2[NH2];
    __shared__ float sb0[NH1];
    __shared__ float sb1[NH2];
    __shared__ float sb2v;
    __shared__ float sx [8][NFEAT];
    __shared__ float sh1[8][NH1];
    __shared__ float sg2[8][NH2];
    __shared__ float sg1[8][NH1];

    const int tid = threadIdx.x;
    const int w   = tid >> 5;
    const int l   = tid & 31;

    const int base = blockIdx.x * 8;
    const int b    = base / NATOM;
    const int a0   = base % NATOM;
    const int t    = a0 / NPT;

    for (int i = tid; i < NH1 * NFEAT; i += 256) {
        int r = i / NFEAT, c = i - r * NFEAT;
        sW0[r * 43 + c] = W0[t * NH1 * NFEAT + i];
    }
    for (int i = tid; i < NH2 * NH1; i += 256) {
        int r = i >> 6, c = i & 63;
        sW1[r * 65 + c] = W1[t * NH2 * NH1 + i];
    }
    if (tid < NH2) sW2[tid] = W2[t * NH2 + tid];
    if (tid < NH1) sb0[tid] = b0[t * NH1 + tid];
    if (tid < NH2) sb1[tid] = b1[t * NH2 + tid];
    if (tid == 0)  sb2v = b2[t];
    __syncthreads();

    const int gidx = b * NATOM + (a0 + w);

    if (l < NFEAT)      sx[w][l]      = image[(long)gidx * NFEAT + l];
    if (l < NFEAT - 32) sx[w][32 + l] = image[(long)gidx * NFEAT + 32 + l];
    __syncwarp();

    float s1 = sb0[l], s2 = sb0[32 + l];
    #pragma unroll
    for (int f = 0; f < NFEAT; f++) {
        const float xv = sx[w][f];
        s1 += xv * sW0[l * 43 + f];
        s2 += xv * sW0[(32 + l) * 43 + f];
    }
    const float h1a = tanhf(s1), h1b = tanhf(s2);
    sh1[w][l] = h1a; sh1[w][32 + l] = h1b;
    __syncwarp();

    float s = sb1[l];
    #pragma unroll
    for (int i = 0; i < NH1; i++) s += sh1[w][i] * sW1[l * 65 + i];
    const float h2 = tanhf(s);
    const float w2v = sW2[l];
    sg2[w][l] = w2v * (1.0f - h2 * h2);

    float v = h2 * w2v;
    #pragma unroll
    for (int o = 16; o > 0; o >>= 1) v += __shfl_down_sync(0xffffffffu, v, o);
    if (l == 0) out[8 + gidx] = v + sb2v;
    __syncwarp();

    float t1 = 0.0f, t2 = 0.0f;
    #pragma unroll
    for (int j = 0; j < NH2; j++) {
        const float gv = sg2[w][j];
        t1 += gv * sW1[j * 65 + l];
        t2 += gv * sW1[j * 65 + 32 + l];
    }
    sg1[w][l]      = t1 * (1.0f - h1a * h1a);
    sg1[w][32 + l] = t2 * (1.0f - h1b * h1b);
    __syncwarp();

    const int c2 = (l < NFEAT - 32) ? (32 + l) : 0;
    float d1 = 0.0f, d2 = 0.0f;
    #pragma unroll
    for (int i = 0; i < NH1; i++) {
        const float gv = sg1[w][i];
        d1 += gv * sW0[i * 43 + l];
        d2 += gv * sW0[i * 43 + c2];
    }
    if (l < NFEAT)      g_dE[(long)gidx * NFEAT + l]      = d1;
    if (l < NFEAT - 32) g_dE[(long)gidx * NFEAT + 32 + l] = d2;
}

// ---------------------------------------------------------------------------
// Kernel 2: Force. 4096 blocks x 384 threads (384 % 3 == 0 is load-bearing).
// Fully-coalesced LDG.128 over the atom tile viewed as 3150 float4s.
// Slot s of float4 q has k = (q+s) mod 3; since q mod 3 == tid mod 3 is a
// per-thread constant, each thread keeps 4 fixed slot accumulators and maps
// them to (x,y,z) once at the end. sg multipliers come from SMEM at
// m = 4*tid/3 + 512*it (exact), with per-thread-constant {0,1} offsets.
// Blocks 0..7 also fold in the Etot reduction (deterministic order).
// ---------------------------------------------------------------------------
__global__ __launch_bounds__(FT) void force_kernel(
    const float* __restrict__ dfeat,
    const int* __restrict__ neighbor,
    float* __restrict__ out)
{
    __shared__ float sg[NPAIR];          // 4200 gathered dE values
    __shared__ int   sn[NNEIGH];
    __shared__ float red[FT / 32][3];
    __shared__ float sred[8];

    const int tid  = threadIdx.x;
    const int gidx = blockIdx.x;             // b*NATOM + a
    const int b    = gidx / NATOM;

    if (tid < NNEIGH)
        sn[tid] = neighbor[(long)gidx * NNEIGH + tid];

    // fused Etot partial (blocks 0..7, first 256 threads): deterministic
    if (gidx < NB && tid < 256) {
        const float* Ei = out + 8 + (long)gidx * NATOM;
        float v = Ei[tid] + Ei[tid + 256];
        #pragma unroll
        for (int o = 16; o > 0; o >>= 1) v += __shfl_down_sync(0xffffffffu, v, o);
        if ((tid & 31) == 0) sred[tid >> 5] = v;
    }
    __syncthreads();

    // Gather: one L2 load per (n,f) pair; index 0 -> zero pad row
    for (int p = tid; p < NPAIR; p += FT) {
        const int n = p / NFEAT;
        const int f = p - n * NFEAT;
        const int j = sn[n];
        sg[p] = j ? g_dE[((long)b * NATOM + (j - 1)) * NFEAT + f] : 0.0f;
    }
    __syncthreads();

    if (gidx < NB && tid == 0) {
        float s = 0.0f;
        #pragma unroll
        for (int ww = 0; ww < 8; ww++) s += sred[ww];
        out[gidx] = s;
    }

    const float4* __restrict__ df = (const float4*)(dfeat + (long)gidx * (NPAIR * 3));

    const int phase = tid % 3;               // == q mod 3 for all iterations
    const int thr   = 3 - phase;             // slot s uses sg[m+1] iff s >= thr
    const int o0 = (0 >= thr) ? 1 : 0;
    const int o1 = (1 >= thr) ? 1 : 0;
    const int o2 = (2 >= thr) ? 1 : 0;
    const int o3 = 1;                        // s=3 always >= thr (thr <= 3)
    const int m0 = (4 * tid) / 3;

    float a0 = 0.0f, a1 = 0.0f, a2 = 0.0f, a3 = 0.0f;

    // 8 unconditional iterations: q = tid + it*384 <= 383+2688 = 3071 < 3150
    #pragma unroll
    for (int it = 0; it < 8; it++) {
        const int q = tid + it * FT;
        const int m = m0 + it * 512;
        const float4 v = df[q];
        a0 += sg[m + o0] * v.x;
        a1 += sg[m + o1] * v.y;
        a2 += sg[m + o2] * v.z;
        a3 += sg[m + o3] * v.w;
    }
    // tail: it = 8, valid iff tid < 3150 - 3072 = 78
    if (tid < NQ - 8 * FT) {
        const int q = tid + 8 * FT;
        const int m = m0 + 8 * 512;
        const float4 v = df[q];
        a0 += sg[m + o0] * v.x;
        a1 += sg[m + o1] * v.y;
        a2 += sg[m + o2] * v.z;
        a3 += sg[m + o3] * v.w;
    }

    // map slot accumulators to (x,y,z):  k(s) = (phase + s) mod 3
    float ax, ay, az;
    if (phase == 0)      { ax = a0 + a3; ay = a1;      az = a2;      }
    else if (phase == 1) { ax = a2;      ay = a0 + a3; az = a1;      }
    else                 { ax = a1;      ay = a2;      az = a0 + a3; }

    #pragma unroll
    for (int o = 16; o > 0; o >>= 1) {
        ax += __shfl_down_sync(0xffffffffu, ax, o);
        ay += __shfl_down_sync(0xffffffffu, ay, o);
        az += __shfl_down_sync(0xffffffffu, az, o);
    }
    const int w = tid >> 5, l = tid & 31;
    if (l == 0) { red[w][0] = ax; red[w][1] = ay; red[w][2] = az; }
    __syncthreads();
    if (tid < 3) {
        float s = 0.0f;
        #pragma unroll
        for (int ww = 0; ww < FT / 32; ww++) s += red[ww][tid];
        out[8 + NB * NATOM + (long)gidx * 3 + tid] = s;
    }
}

// ---------------------------------------------------------------------------
// Launch: out layout = [Etot(8) | Ei(4096) | Force(12288)] = 16392 f32
// ---------------------------------------------------------------------------
extern "C" void kernel_launch(void* const* d_in, const int* in_sizes, int n_in,
                              void* d_out, int out_size)
{
    const float* image    = (const float*)d_in[0];
    const float* dfeat    = (const float*)d_in[1];
    const int*   neighbor = (const int*)d_in[2];
    // d_in[3] = natoms_img (unused)
    const float* W0 = (const float*)d_in[4];
    const float* b0 = (const float*)d_in[5];
    const float* W1 = (const float*)d_in[6];
    const float* b1 = (const float*)d_in[7];
    const float* W2 = (const float*)d_in[8];
    const float* b2 = (const float*)d_in[9];
    float* out = (float*)d_out;

    ei_kernel<<<(NB * NATOM) / 8, 256>>>(image, W0, b0, W1, b1, W2, b2, out);
    force_kernel<<<NB * NATOM, FT>>>(dfeat, neighbor, out);
}